// round 12
// baseline (speedup 1.0000x reference)
#include <cuda_runtime.h>

#define BATCH 16
#define NPTS  8192
#define NSEL  1024
#define NSAMP 32
#define NROWS (BATCH*NSEL*NSAMP)   /* 524288 */
#define PAD 68                     /* mma pad (A-fragment conflict-free)    */

/* ------------------------------- scratch ------------------------------- */
__device__ __align__(16) int   g_gidx[BATCH*NSEL*NSAMP];
__device__ __align__(16) float g_ptsT[(size_t)BATCH*NPTS*64];
__device__ __align__(16) float g_y0[(size_t)NROWS*64];
__device__ __align__(16) float g_y1[(size_t)NROWS*64];
__device__ __align__(16) float g_max2[BATCH*NSEL*128];
__device__ __align__(16) float g_min2[BATCH*NSEL*128];
__device__ float g_sum[3][128], g_ssq[3][128];
__device__ float g_a[3][128],  g_c[3][128];

/* tf32 round (matches TF32 gemm input quantization) */
__device__ __forceinline__ float tf32r(float x)
{
    unsigned u; asm("cvt.rna.tf32.f32 %0, %1;" : "=r"(u) : "f"(x));
    return __uint_as_float(u);
}

/* distance matching XLA-GPU fused form: fma(dz,dz, fma(dy,dy, dx*dx)) */
__device__ __forceinline__ float dist3(float ax, float ay, float az,
                                       float bx, float by, float bz)
{
    float dx = __fsub_rn(ax, bx);
    float dy = __fsub_rn(ay, by);
    float dz = __fsub_rn(az, bz);
    return __fmaf_rn(dz, dz, __fmaf_rn(dy, dy, __fmul_rn(dx, dx)));
}

__device__ __forceinline__ unsigned redux_max_u32(unsigned v)
{
    unsigned r;
    asm("redux.sync.max.u32 %0, %1, 0xffffffff;" : "=r"(r) : "r"(v));
    return r;
}
__device__ __forceinline__ unsigned redux_min_u32(unsigned v)
{
    unsigned r;
    asm("redux.sync.min.u32 %0, %1, 0xffffffff;" : "=r"(r) : "r"(v));
    return r;
}

/* tf32 warp mma: D(16x8) += A(16x8) * B(8x8) */
__device__ __forceinline__ void mma_tf32(float& d0, float& d1, float& d2, float& d3,
                                         unsigned a0, unsigned a1, unsigned a2, unsigned a3,
                                         unsigned b0, unsigned b1)
{
    asm("mma.sync.aligned.m16n8k8.row.col.f32.tf32.tf32.f32 "
        "{%0,%1,%2,%3}, {%4,%5,%6,%7}, {%8,%9}, {%0,%1,%2,%3};"
        : "+f"(d0), "+f"(d1), "+f"(d2), "+f"(d3)
        : "r"(a0), "r"(a1), "r"(a2), "r"(a3), "r"(b0), "r"(b1));
}

/* ------------------------------- zero stats ---------------------------- */
__global__ void k_zero()
{
    int i = threadIdx.x;
    if (i < 128){
        g_sum[0][i]=0.f; g_ssq[0][i]=0.f;
        g_sum[1][i]=0.f; g_ssq[1][i]=0.f;
        g_sum[2][i]=0.f; g_ssq[2][i]=0.f;
    }
}

/* ------------------------------- FPS ----------------------------------- */
/* ONE barrier/iter: per-warp redux max + redux-min index, cross-warp via  */
/* shared u64 atomicMax key=(dist<<32)|(~idx); 3-slot rotation for reset.  */
__global__ __launch_bounds__(1024) void k_fps(const float* __restrict__ xyz,
                                              float* __restrict__ out)
{
    extern __shared__ float4 sX[];          /* 8192 * 16B = 128 KB */
    __shared__ unsigned long long sS[3];
    int b = blockIdx.x, t = threadIdx.x;
    const float* X = xyz + (size_t)b*NPTS*3;
    float px[8], py[8], pz[8], dist[8];
#pragma unroll
    for (int j = 0; j < 8; j++){
        int p = t + j*1024;
        float x = X[p*3+0], y = X[p*3+1], z = X[p*3+2];
        px[j]=x; py[j]=y; pz[j]=z; dist[j]=1e10f;
        sX[p] = make_float4(x, y, z, 0.f);
    }
    if (t == 0){
        sS[0] = 0xFFFFFFFFull;   /* idx field: 0xFFFFFFFF - 0 -> best = 0 */
        sS[1] = 0ull; sS[2] = 0ull;
    }
    __syncthreads();
    for (int i = 0; i < NSEL; i++){
        int p = i % 3;
        unsigned long long key = sS[p];
        int best = (int)(0xFFFFFFFFu - (unsigned)(key & 0xFFFFFFFFull));
        float4 c = sX[best];
        if (t == 0){
            float* o = out + ((size_t)b*NSEL + i)*3;
            o[0]=c.x; o[1]=c.y; o[2]=c.z;
        }
        unsigned tmu = 0u;
#pragma unroll
        for (int j = 0; j < 8; j++){
            float d  = dist3(px[j], py[j], pz[j], c.x, c.y, c.z);
            float nd = fminf(dist[j], d);
            dist[j]  = nd;
            unsigned ub = __float_as_uint(nd);
            tmu = (ub > tmu) ? ub : tmu;
        }
        unsigned wmax = redux_max_u32(tmu);
        int li = 0x7fffffff;
#pragma unroll
        for (int j = 7; j >= 0; j--)
            if (__float_as_uint(dist[j]) == wmax) li = t + j*1024; /* lowest */
        unsigned lmin = redux_min_u32((unsigned)li);
        if ((t & 31) == 0)
            atomicMax(&sS[(p+1)%3],
                      ((unsigned long long)wmax << 32) |
                      (unsigned long long)(0xFFFFFFFFu - lmin));
        if (t == 0) sS[(p+2)%3] = 0ull;   /* read in iter i-1; next write i+1 */
        __syncthreads();
    }
}

/* ---------------------- transpose points (B,C,N)->(B,N,C) --------------- */
__global__ void k_tr(const float* __restrict__ pts)
{
    __shared__ float t[32][33];
    int b = blockIdx.z;
    int n0 = blockIdx.x*32, c0 = blockIdx.y*32;
    const float* src = pts + (size_t)b*64*NPTS;
    for (int i = threadIdx.y; i < 32; i += 8)
        t[i][threadIdx.x] = src[(size_t)(c0+i)*NPTS + n0 + threadIdx.x];
    __syncthreads();
    float* dst = g_ptsT + (size_t)b*NPTS*64;
    for (int i = threadIdx.y; i < 32; i += 8)
        dst[(size_t)(n0+i)*64 + c0 + threadIdx.x] = t[threadIdx.x][i];
}

/* ------------------------------- ball query ----------------------------- */
__global__ __launch_bounds__(1024) void k_ball(const float* __restrict__ xyz,
                                               const float* __restrict__ nx)
{
    extern __shared__ float4 sP[];          /* 8192 * 16B = 128 KB */
    int b   = blockIdx.x >> 3;
    int sub = blockIdx.x & 7;
    const float* X = xyz + (size_t)b*NPTS*3;
    for (int p = threadIdx.x; p < NPTS; p += 1024)
        sP[p] = make_float4(X[p*3+0], X[p*3+1], X[p*3+2], 0.f);
    __syncthreads();
    int w = threadIdx.x >> 5, lane = threadIdx.x & 31;
    const float r2 = 0.04f;
#pragma unroll
    for (int ci = 0; ci < 4; ci++){
        int s   = sub*128 + w*4 + ci;
        int wid = b*NSEL + s;
        float cx = nx[wid*3+0], cy = nx[wid*3+1], cz = nx[wid*3+2];
        int* out = g_gidx + (size_t)wid*NSAMP;
        int cnt = 0, firstn = 0;
        for (int n0 = 0; n0 < NPTS; n0 += 32){
            float4 p = sP[n0 + lane];
            float d = dist3(p.x, p.y, p.z, cx, cy, cz);
            bool in = !(d > r2);
            unsigned m = __ballot_sync(0xffffffffu, in);
            if (m){
                if (cnt == 0) firstn = n0 + __ffs(m) - 1;
                int pre = __popc(m & ((1u << lane) - 1u));
                if (in && cnt + pre < NSAMP) out[cnt + pre] = n0 + lane;
                cnt += __popc(m);
                if (cnt >= NSAMP) break;
            }
        }
        for (int p = cnt + lane; p < NSAMP; p += 32) out[p] = firstn;
    }
}

/* ------------------------------- affine fold ---------------------------- */
__global__ void k_affine(int L, const float* __restrict__ g,
                         const float* __restrict__ beta, int C)
{
    int i = threadIdx.x;
    if (i < C){
        float inv  = 1.f / (float)NROWS;
        float mean = g_sum[L][i] * inv;
        float var  = g_ssq[L][i] * inv - mean*mean;
        var = fmaxf(var, 0.f);
        float a = g[i] * rsqrtf(var + 1e-5f);
        g_a[L][i] = a;
        g_c[L][i] = beta[i] - mean*a;
    }
}

/* ------------- GEMM layer 0 (gather, tf32 mma + 3-tap tail) ------------- */
__global__ __launch_bounds__(256) void k_gemm0(const float* __restrict__ xyz,
                                               const float* __restrict__ nx,
                                               const float* __restrict__ w,
                                               const float* __restrict__ bias)
{
    extern __shared__ float sm[];
    float* xs = sm;                       /* 256 * 68 (67 used) */
    float* wf = sm + 256*PAD;             /* 4096 fragment-ordered (k<64) */
    float* w3 = wf + 4096;                /* 3*64 tail weights (k=64..66) */
    __shared__ float sSum[64], sSq[64], sBias[64];
    int tid = threadIdx.x;
    if (tid < 64){ sSum[tid]=0.f; sSq[tid]=0.f; sBias[tid]=bias[tid]; }
    for (int i = tid; i < 4096; i += 256){
        int h = i & 1, ln = (i>>1)&31, pr = i>>6;
        int kb = pr>>3, nb = pr&7, gd = ln>>2, tg = ln&3;
        wf[i] = tf32r(w[(nb*8+gd)*67 + kb*8+tg + h*4]);
    }
    for (int i = tid; i < 192; i += 256){
        int kk = i >> 6, o = i & 63;
        w3[i] = tf32r(w[o*67 + 64 + kk]);
    }
    {   /* gather one row per thread */
        int gs  = blockIdx.x*8 + (tid >> 5);
        int k   = tid & 31;
        int b   = gs >> 10;
        int pid = g_gidx[gs*NSAMP + k];
        const float4* src = (const float4*)(g_ptsT + ((size_t)b*NPTS + pid)*64);
        float* xr = xs + tid*PAD;
#pragma unroll
        for (int q = 0; q < 16; q++){
            float4 v = src[q];
            xr[q*4+0]=tf32r(v.x); xr[q*4+1]=tf32r(v.y);
            xr[q*4+2]=tf32r(v.z); xr[q*4+3]=tf32r(v.w);
        }
        const float* P = xyz + ((size_t)b*NPTS + pid)*3;
        const float* C = nx + (size_t)gs*3;
        xr[64] = tf32r(__fsub_rn(P[0], C[0]));
        xr[65] = tf32r(__fsub_rn(P[1], C[1]));
        xr[66] = tf32r(__fsub_rn(P[2], C[2]));
    }
    __syncthreads();
    int lane = tid & 31, wp = tid >> 5;
    int gid = lane >> 2, tig = lane & 3;
    float sl[16], ql[16];
#pragma unroll
    for (int i = 0; i < 16; i++){ sl[i]=0.f; ql[i]=0.f; }
    size_t rbase = (size_t)blockIdx.x*256 + wp*32;
#pragma unroll
    for (int hh = 0; hh < 2; hh++){
        int lm0 = wp*32 + hh*16;
        float d[8][4];
#pragma unroll
        for (int nb = 0; nb < 8; nb++){
            d[nb][0]=sBias[nb*8+2*tig]; d[nb][1]=sBias[nb*8+2*tig+1];
            d[nb][2]=d[nb][0]; d[nb][3]=d[nb][1];
        }
#pragma unroll
        for (int kb = 0; kb < 8; kb++){
            const float* ar = xs + (lm0+gid)*PAD + kb*8 + tig;
            unsigned a0 = __float_as_uint(ar[0]);
            unsigned a2 = __float_as_uint(ar[4]);
            unsigned a1 = __float_as_uint(ar[8*PAD]);
            unsigned a3 = __float_as_uint(ar[8*PAD+4]);
#pragma unroll
            for (int nb = 0; nb < 8; nb++){
                float2 bp = *(const float2*)(wf + ((kb*8+nb)*32 + lane)*2);
                mma_tf32(d[nb][0], d[nb][1], d[nb][2], d[nb][3],
                         a0, a1, a2, a3,
                         __float_as_uint(bp.x), __float_as_uint(bp.y));
            }
        }
        /* 3-tap tail: k = 64..66 */
        {
            const float* xa = xs + (lm0+gid)*PAD + 64;
            const float* xb = xs + (lm0+gid+8)*PAD + 64;
            float xa0=xa[0], xa1=xa[1], xa2=xa[2];
            float xb0=xb[0], xb1=xb[1], xb2=xb[2];
#pragma unroll
            for (int nb = 0; nb < 8; nb++){
                int col = nb*8 + 2*tig;
                float w00=w3[col],     w01=w3[col+1];
                float w10=w3[64+col],  w11=w3[64+col+1];
                float w20=w3[128+col], w21=w3[128+col+1];
                d[nb][0] = fmaf(xa2,w20, fmaf(xa1,w10, fmaf(xa0,w00, d[nb][0])));
                d[nb][1] = fmaf(xa2,w21, fmaf(xa1,w11, fmaf(xa0,w01, d[nb][1])));
                d[nb][2] = fmaf(xb2,w20, fmaf(xb1,w10, fmaf(xb0,w00, d[nb][2])));
                d[nb][3] = fmaf(xb2,w21, fmaf(xb1,w11, fmaf(xb0,w01, d[nb][3])));
            }
        }
        size_t r0 = rbase + hh*16;
#pragma unroll
        for (int nb = 0; nb < 8; nb++){
            int col = nb*8 + 2*tig;
            *(float2*)(g_y0 + (r0+gid)*64   + col) = make_float2(d[nb][0], d[nb][1]);
            *(float2*)(g_y0 + (r0+gid+8)*64 + col) = make_float2(d[nb][2], d[nb][3]);
            sl[nb*2]   += d[nb][0]+d[nb][2];
            sl[nb*2+1] += d[nb][1]+d[nb][3];
            ql[nb*2]   = fmaf(d[nb][0],d[nb][0], fmaf(d[nb][2],d[nb][2], ql[nb*2]));
            ql[nb*2+1] = fmaf(d[nb][1],d[nb][1], fmaf(d[nb][3],d[nb][3], ql[nb*2+1]));
        }
    }
#pragma unroll
    for (int off = 4; off <= 16; off <<= 1)
#pragma unroll
        for (int i = 0; i < 16; i++){
            sl[i] += __shfl_xor_sync(0xffffffffu, sl[i], off);
            ql[i] += __shfl_xor_sync(0xffffffffu, ql[i], off);
        }
    if (gid == 0)
#pragma unroll
        for (int nb = 0; nb < 8; nb++){
            atomicAdd(&sSum[nb*8+2*tig],   sl[nb*2]);
            atomicAdd(&sSum[nb*8+2*tig+1], sl[nb*2+1]);
            atomicAdd(&sSq [nb*8+2*tig],   ql[nb*2]);
            atomicAdd(&sSq [nb*8+2*tig+1], ql[nb*2+1]);
        }
    __syncthreads();
    if (tid < 64){
        atomicAdd(&g_sum[0][tid], sSum[tid]);
        atomicAdd(&g_ssq[0][tid], sSq[tid]);
    }
}

/* ------------------- GEMM layer 1 (tf32 tensor mma) --------------------- */
__global__ __launch_bounds__(256) void k_gemm1(const float* __restrict__ w,
                                               const float* __restrict__ bias)
{
    extern __shared__ float sm[];
    float* xs = sm;                       /* 256 * 68 */
    float* wf = sm + 256*PAD;             /* 4096 fragment-ordered */
    __shared__ float sSum[64], sSq[64], sA[64], sC[64], sBias[64];
    int tid = threadIdx.x;
    if (tid < 64){
        sSum[tid]=0.f; sSq[tid]=0.f;
        sA[tid]=g_a[0][tid]; sC[tid]=g_c[0][tid]; sBias[tid]=bias[tid];
    }
    for (int i = tid; i < 4096; i += 256){
        int h = i & 1, ln = (i>>1)&31, pr = i>>6;
        int kb = pr>>3, nb = pr&7, gd = ln>>2, tg = ln&3;
        wf[i] = tf32r(w[(nb*8+gd)*64 + kb*8+tg + h*4]);
    }
    __syncthreads();
    {
        size_t row = (size_t)blockIdx.x*256 + tid;
        const float4* src = (const float4*)(g_y0 + row*64);
        float* xr = xs + tid*PAD;
#pragma unroll
        for (int q = 0; q < 16; q++){
            float4 v = src[q];
            xr[q*4+0]=tf32r(fmaxf(fmaf(sA[q*4+0],v.x,sC[q*4+0]),0.f));
            xr[q*4+1]=tf32r(fmaxf(fmaf(sA[q*4+1],v.y,sC[q*4+1]),0.f));
            xr[q*4+2]=tf32r(fmaxf(fmaf(sA[q*4+2],v.z,sC[q*4+2]),0.f));
            xr[q*4+3]=tf32r(fmaxf(fmaf(sA[q*4+3],v.w,sC[q*4+3]),0.f));
        }
    }
    __syncthreads();
    int lane = tid & 31, wp = tid >> 5;
    int gid = lane >> 2, tig = lane & 3;
    float sl[16], ql[16];
#pragma unroll
    for (int i = 0; i < 16; i++){ sl[i]=0.f; ql[i]=0.f; }
    size_t rbase = (size_t)blockIdx.x*256 + wp*32;
#pragma unroll
    for (int hh = 0; hh < 2; hh++){
        int lm0 = wp*32 + hh*16;
        float d[8][4];
#pragma unroll
        for (int nb = 0; nb < 8; nb++){
            d[nb][0]=sBias[nb*8+2*tig]; d[nb][1]=sBias[nb*8+2*tig+1];
            d[nb][2]=d[nb][0]; d[nb][3]=d[nb][1];
        }
#pragma unroll
        for (int kb = 0; kb < 8; kb++){
            const float* ar = xs + (lm0+gid)*PAD + kb*8 + tig;
            unsigned a0 = __float_as_uint(ar[0]);
            unsigned a2 = __float_as_uint(ar[4]);
            unsigned a1 = __float_as_uint(ar[8*PAD]);
            unsigned a3 = __float_as_uint(ar[8*PAD+4]);
#pragma unroll
            for (int nb = 0; nb < 8; nb++){
                float2 bp = *(const float2*)(wf + ((kb*8+nb)*32 + lane)*2);
                mma_tf32(d[nb][0], d[nb][1], d[nb][2], d[nb][3],
                         a0, a1, a2, a3,
                         __float_as_uint(bp.x), __float_as_uint(bp.y));
            }
        }
        size_t r0 = rbase + hh*16;
#pragma unroll
        for (int nb = 0; nb < 8; nb++){
            int col = nb*8 + 2*tig;
            *(float2*)(g_y1 + (r0+gid)*64   + col) = make_float2(d[nb][0], d[nb][1]);
            *(float2*)(g_y1 + (r0+gid+8)*64 + col) = make_float2(d[nb][2], d[nb][3]);
            sl[nb*2]   += d[nb][0]+d[nb][2];
            sl[nb*2+1] += d[nb][1]+d[nb][3];
            ql[nb*2]   = fmaf(d[nb][0],d[nb][0], fmaf(d[nb][2],d[nb][2], ql[nb*2]));
            ql[nb*2+1] = fmaf(d[nb][1],d[nb][1], fmaf(d[nb][3],d[nb][3], ql[nb*2+1]));
        }
    }
#pragma unroll
    for (int off = 4; off <= 16; off <<= 1)
#pragma unroll
        for (int i = 0; i < 16; i++){
            sl[i] += __shfl_xor_sync(0xffffffffu, sl[i], off);
            ql[i] += __shfl_xor_sync(0xffffffffu, ql[i], off);
        }
    if (gid == 0)
#pragma unroll
        for (int nb = 0; nb < 8; nb++){
            atomicAdd(&sSum[nb*8+2*tig],   sl[nb*2]);
            atomicAdd(&sSum[nb*8+2*tig+1], sl[nb*2+1]);
            atomicAdd(&sSq [nb*8+2*tig],   ql[nb*2]);
            atomicAdd(&sSq [nb*8+2*tig+1], ql[nb*2+1]);
        }
    __syncthreads();
    if (tid < 64){
        atomicAdd(&g_sum[1][tid], sSum[tid]);
        atomicAdd(&g_ssq[1][tid], sSq[tid]);
    }
}

/* --------------- GEMM layer 2 (tf32 mma, max/min fused) ----------------- */
__global__ __launch_bounds__(256) void k_gemm2(const float* __restrict__ w,
                                               const float* __restrict__ bias)
{
    extern __shared__ float sm[];
    float* xs = sm;
    float* wf = sm + 256*PAD;
    __shared__ float sSum[64], sSq[64], sA[64], sC[64], sBias[64];
    int tid = threadIdx.x;
    int half = blockIdx.y;
    if (tid < 64){
        sSum[tid]=0.f; sSq[tid]=0.f;
        sA[tid]=g_a[1][tid]; sC[tid]=g_c[1][tid]; sBias[tid]=bias[half*64+tid];
    }
    for (int i = tid; i < 4096; i += 256){
        int h = i & 1, ln = (i>>1)&31, pr = i>>6;
        int kb = pr>>3, nb = pr&7, gd = ln>>2, tg = ln&3;
        wf[i] = tf32r(w[(size_t)(half*64 + nb*8+gd)*64 + kb*8+tg + h*4]);
    }
    __syncthreads();
    {
        size_t row = (size_t)blockIdx.x*256 + tid;
        const float4* src = (const float4*)(g_y1 + row*64);
        float* xr = xs + tid*PAD;
#pragma unroll
        for (int q = 0; q < 16; q++){
            float4 v = src[q];
            xr[q*4+0]=tf32r(fmaxf(fmaf(sA[q*4+0],v.x,sC[q*4+0]),0.f));
            xr[q*4+1]=tf32r(fmaxf(fmaf(sA[q*4+1],v.y,sC[q*4+1]),0.f));
            xr[q*4+2]=tf32r(fmaxf(fmaf(sA[q*4+2],v.z,sC[q*4+2]),0.f));
            xr[q*4+3]=tf32r(fmaxf(fmaf(sA[q*4+3],v.w,sC[q*4+3]),0.f));
        }
    }
    __syncthreads();
    int lane = tid & 31, wp = tid >> 5;
    int gid = lane >> 2, tig = lane & 3;
    float sl[16], ql[16], mx[16], mn[16];
#pragma unroll
    for (int i = 0; i < 16; i++){ sl[i]=0.f; ql[i]=0.f; mx[i]=-3.4e38f; mn[i]=3.4e38f; }
#pragma unroll
    for (int hh = 0; hh < 2; hh++){
        int lm0 = wp*32 + hh*16;
        float d[8][4];
#pragma unroll
        for (int nb = 0; nb < 8; nb++){
            d[nb][0]=sBias[nb*8+2*tig]; d[nb][1]=sBias[nb*8+2*tig+1];
            d[nb][2]=d[nb][0]; d[nb][3]=d[nb][1];
        }
#pragma unroll
        for (int kb = 0; kb < 8; kb++){
            const float* ar = xs + (lm0+gid)*PAD + kb*8 + tig;
            unsigned a0 = __float_as_uint(ar[0]);
            unsigned a2 = __float_as_uint(ar[4]);
            unsigned a1 = __float_as_uint(ar[8*PAD]);
            unsigned a3 = __float_as_uint(ar[8*PAD+4]);
#pragma unroll
            for (int nb = 0; nb < 8; nb++){
                float2 bp = *(const float2*)(wf + ((kb*8+nb)*32 + lane)*2);
                mma_tf32(d[nb][0], d[nb][1], d[nb][2], d[nb][3],
                         a0, a1, a2, a3,
                         __float_as_uint(bp.x), __float_as_uint(bp.y));
            }
        }
#pragma unroll
        for (int nb = 0; nb < 8; nb++){
            sl[nb*2]   += d[nb][0]+d[nb][2];
            sl[nb*2+1] += d[nb][1]+d[nb][3];
            ql[nb*2]   = fmaf(d[nb][0],d[nb][0], fmaf(d[nb][2],d[nb][2], ql[nb*2]));
            ql[nb*2+1] = fmaf(d[nb][1],d[nb][1], fmaf(d[nb][3],d[nb][3], ql[nb*2+1]));
            mx[nb*2]   = fmaxf(mx[nb*2],   fmaxf(d[nb][0], d[nb][2]));
            mx[nb*2+1] = fmaxf(mx[nb*2+1], fmaxf(d[nb][1], d[nb][3]));
            mn[nb*2]   = fminf(mn[nb*2],   fminf(d[nb][0], d[nb][2]));
            mn[nb*2+1] = fminf(mn[nb*2+1], fminf(d[nb][1], d[nb][3]));
        }
    }
#pragma unroll
    for (int off = 4; off <= 16; off <<= 1)
#pragma unroll
        for (int i = 0; i < 16; i++){
            sl[i] += __shfl_xor_sync(0xffffffffu, sl[i], off);
            ql[i] += __shfl_xor_sync(0xffffffffu, ql[i], off);
            mx[i]  = fmaxf(mx[i], __shfl_xor_sync(0xffffffffu, mx[i], off));
            mn[i]  = fminf(mn[i], __shfl_xor_sync(0xffffffffu, mn[i], off));
        }
    if (gid == 0){
        int grp = blockIdx.x*8 + wp;
        float* M = g_max2 + (size_t)grp*128 + half*64;
        float* m = g_min2 + (size_t)grp*128 + half*64;
#pragma unroll
        for (int nb = 0; nb < 8; nb++){
            int col = nb*8 + 2*tig;
            *(float2*)(M + col) = make_float2(mx[nb*2], mx[nb*2+1]);
            *(float2*)(m + col) = make_float2(mn[nb*2], mn[nb*2+1]);
            atomicAdd(&sSum[col],   sl[nb*2]);
            atomicAdd(&sSum[col+1], sl[nb*2+1]);
            atomicAdd(&sSq [col],   ql[nb*2]);
            atomicAdd(&sSq [col+1], ql[nb*2+1]);
        }
    }
    __syncthreads();
    if (tid < 64){
        atomicAdd(&g_sum[2][half*64+tid], sSum[tid]);
        atomicAdd(&g_ssq[2][half*64+tid], sSq[tid]);
    }
}

/* ----------------------- final BN+relu+max -> (B,128,1024) -------------- */
__global__ void k_out(float* __restrict__ out)
{
    int idx = blockIdx.x*blockDim.x + threadIdx.x;
    int b = idx >> 17, o = (idx >> 10) & 127, s = idx & 1023;
    float a = g_a[2][o], c = g_c[2][o];
    size_t gi = ((size_t)(b*NSEL + s))*128 + o;
    float v = (a >= 0.f) ? g_max2[gi] : g_min2[gi];
    out[idx] = fmaxf(fmaf(a, v, c), 0.f);
}

/* ------------------------------- launch --------------------------------- */
extern "C" void kernel_launch(void* const* d_in, const int* in_sizes, int n_in,
                              void* d_out, int out_size)
{
    (void)in_sizes; (void)n_in; (void)out_size;
    const float* xyz = (const float*)d_in[0];
    const float* pts = (const float*)d_in[1];
    const float* w0  = (const float*)d_in[2];
    const float* b0  = (const float*)d_in[3];
    const float* gg0 = (const float*)d_in[4];
    const float* be0 = (const float*)d_in[5];
    const float* w1  = (const float*)d_in[6];
    const float* b1  = (const float*)d_in[7];
    const float* gg1 = (const float*)d_in[8];
    const float* be1 = (const float*)d_in[9];
    const float* w2  = (const float*)d_in[10];
    const float* b2  = (const float*)d_in[11];
    const float* gg2 = (const float*)d_in[12];
    const float* be2 = (const float*)d_in[13];
    float* out    = (float*)d_out;
    float* newxyz = out;                       /* 16*1024*3 */
    float* newpts = out + BATCH*NSEL*3;        /* 16*128*1024 */

    const int SM_PTS = NPTS * 16;                       /* 131072 */
    const int SM_G0  = (256*PAD + 4096 + 192) * 4;      /* 86784  */
    const int SM_MMA = (256*PAD + 4096) * 4;            /* 86016  */
    cudaFuncSetAttribute(k_fps,   cudaFuncAttributeMaxDynamicSharedMemorySize, SM_PTS);
    cudaFuncSetAttribute(k_ball,  cudaFuncAttributeMaxDynamicSharedMemorySize, SM_PTS);
    cudaFuncSetAttribute(k_gemm0, cudaFuncAttributeMaxDynamicSharedMemorySize, SM_G0);
    cudaFuncSetAttribute(k_gemm1, cudaFuncAttributeMaxDynamicSharedMemorySize, SM_MMA);
    cudaFuncSetAttribute(k_gemm2, cudaFuncAttributeMaxDynamicSharedMemorySize, SM_MMA);

    k_zero<<<1, 128>>>();
    k_fps <<<BATCH, 1024, SM_PTS>>>(xyz, newxyz);
    k_tr  <<<dim3(NPTS/32, 2, BATCH), dim3(32, 8)>>>(pts);
    k_ball<<<BATCH*8, 1024, SM_PTS>>>(xyz, newxyz);
    k_gemm0<<<NROWS/256, 256, SM_G0>>>(xyz, newxyz, w0, b0);
    k_affine<<<1, 128>>>(0, gg0, be0, 64);
    k_gemm1<<<NROWS/256, 256, SM_MMA>>>(w1, b1);
    k_affine<<<1, 128>>>(1, gg1, be1, 64);
    k_gemm2<<<dim3(NROWS/256, 2), 256, SM_MMA>>>(w2, b2);
    k_affine<<<1, 128>>>(2, gg2, be2, 128);
    k_out<<<(BATCH*128*NSEL)/256, 256>>>(newpts);
}

// round 14
// speedup vs baseline: 1.1115x; 1.1115x over previous
#include <cuda_runtime.h>

#define BATCH 16
#define NPTS  8192
#define NSEL  1024
#define NSAMP 32
#define NROWS (BATCH*NSEL*NSAMP)   /* 524288 */
#define PAD 68                     /* mma pad (A-fragment conflict-free)    */

/* ------------------------------- scratch ------------------------------- */
__device__ __align__(16) int   g_gidx[BATCH*NSEL*NSAMP];
__device__ __align__(16) float g_ptsT[(size_t)BATCH*NPTS*64];
__device__ __align__(16) float g_y0[(size_t)NROWS*64];
__device__ __align__(16) float g_y1[(size_t)NROWS*64];
__device__ __align__(16) float g_max2[BATCH*NSEL*128];
__device__ __align__(16) float g_min2[BATCH*NSEL*128];
__device__ float g_sum[3][128], g_ssq[3][128];

/* tf32 round (matches TF32 gemm input quantization) */
__device__ __forceinline__ float tf32r(float x)
{
    unsigned u; asm("cvt.rna.tf32.f32 %0, %1;" : "=r"(u) : "f"(x));
    return __uint_as_float(u);
}

/* distance matching XLA-GPU fused form: fma(dz,dz, fma(dy,dy, dx*dx)) */
__device__ __forceinline__ float dist3(float ax, float ay, float az,
                                       float bx, float by, float bz)
{
    float dx = __fsub_rn(ax, bx);
    float dy = __fsub_rn(ay, by);
    float dz = __fsub_rn(az, bz);
    return __fmaf_rn(dz, dz, __fmaf_rn(dy, dy, __fmul_rn(dx, dx)));
}

__device__ __forceinline__ unsigned redux_max_u32(unsigned v)
{
    unsigned r;
    asm("redux.sync.max.u32 %0, %1, 0xffffffff;" : "=r"(r) : "r"(v));
    return r;
}

/* affine fold: a = g*rsqrt(var+eps), c = beta - mean*a (same as old k_affine) */
__device__ __forceinline__ void affine_fold(float sum, float ssq, float g, float beta,
                                            float& a, float& c)
{
    float inv  = 1.f / (float)NROWS;
    float mean = sum * inv;
    float var  = ssq * inv - mean*mean;
    var = fmaxf(var, 0.f);
    a = g * rsqrtf(var + 1e-5f);
    c = beta - mean*a;
}

/* tf32 warp mma: D(16x8) += A(16x8) * B(8x8) */
__device__ __forceinline__ void mma_tf32(float& d0, float& d1, float& d2, float& d3,
                                         unsigned a0, unsigned a1, unsigned a2, unsigned a3,
                                         unsigned b0, unsigned b1)
{
    asm("mma.sync.aligned.m16n8k8.row.col.f32.tf32.tf32.f32 "
        "{%0,%1,%2,%3}, {%4,%5,%6,%7}, {%8,%9}, {%0,%1,%2,%3};"
        : "+f"(d0), "+f"(d1), "+f"(d2), "+f"(d3)
        : "r"(a0), "r"(a1), "r"(a2), "r"(a3), "r"(b0), "r"(b1));
}

/* ------------------------------- zero stats ---------------------------- */
__global__ void k_zero()
{
    int i = threadIdx.x;
    if (i < 128){
        g_sum[0][i]=0.f; g_ssq[0][i]=0.f;
        g_sum[1][i]=0.f; g_ssq[1][i]=0.f;
        g_sum[2][i]=0.f; g_ssq[2][i]=0.f;
    }
}

/* ------------------------------- FPS ----------------------------------- */
/* R11 version (measured best): redux max, double-buffered sB, 2 barriers */
__global__ __launch_bounds__(1024) void k_fps(const float* __restrict__ xyz,
                                              float* __restrict__ out)
{
    extern __shared__ float4 sX[];          /* 8192 * 16B = 128 KB */
    __shared__ unsigned sW[32];
    __shared__ int sB[2];
    int b = blockIdx.x, t = threadIdx.x;
    const float* X = xyz + (size_t)b*NPTS*3;
    float px[8], py[8], pz[8], dist[8];
#pragma unroll
    for (int j = 0; j < 8; j++){
        int p = t + j*1024;
        float x = X[p*3+0], y = X[p*3+1], z = X[p*3+2];
        px[j]=x; py[j]=y; pz[j]=z; dist[j]=1e10f;
        sX[p] = make_float4(x, y, z, 0.f);
    }
    if (t == 0){ sB[0] = 0; sB[1] = 0x7fffffff; }
    __syncthreads();
    for (int i = 0; i < NSEL; i++){
        int p = i & 1;
        int best = sB[p];
        float4 c = sX[best];
        if (t == 0){
            float* o = out + ((size_t)b*NSEL + i)*3;
            o[0]=c.x; o[1]=c.y; o[2]=c.z;
        }
        unsigned tmu = 0u;
#pragma unroll
        for (int j = 0; j < 8; j++){
            float d  = dist3(px[j], py[j], pz[j], c.x, c.y, c.z);
            float nd = fminf(dist[j], d);
            dist[j]  = nd;
            unsigned ub = __float_as_uint(nd);
            tmu = (ub > tmu) ? ub : tmu;
        }
        unsigned wmax = redux_max_u32(tmu);
        if ((t & 31) == 0) sW[t >> 5] = wmax;
        __syncthreads();                 /* barA: sW ready; sB[p] reads done */
        unsigned gmu = redux_max_u32(sW[t & 31]);   /* every warp, no bcast */
        if (t == 0) sB[p] = 0x7fffffff;  /* re-arm for iter i+2 */
        float gm = __uint_as_float(gmu);
        int li = 0x7fffffff;
#pragma unroll
        for (int j = 7; j >= 0; j--)
            if (dist[j] == gm) li = t + j*1024;  /* descending -> lowest idx */
        if (li != 0x7fffffff) atomicMin(&sB[p^1], li);
        __syncthreads();                 /* barB: sB[p^1] final */
    }
}

/* ---------------------- transpose points (B,C,N)->(B,N,C) --------------- */
__global__ void k_tr(const float* __restrict__ pts)
{
    __shared__ float t[32][33];
    int b = blockIdx.z;
    int n0 = blockIdx.x*32, c0 = blockIdx.y*32;
    const float* src = pts + (size_t)b*64*NPTS;
    for (int i = threadIdx.y; i < 32; i += 8)
        t[i][threadIdx.x] = src[(size_t)(c0+i)*NPTS + n0 + threadIdx.x];
    __syncthreads();
    float* dst = g_ptsT + (size_t)b*NPTS*64;
    for (int i = threadIdx.y; i < 32; i += 8)
        dst[(size_t)(n0+i)*64 + c0 + threadIdx.x] = t[threadIdx.x][i];
}

/* ------------------------------- ball query ----------------------------- */
__global__ __launch_bounds__(1024) void k_ball(const float* __restrict__ xyz,
                                               const float* __restrict__ nx)
{
    extern __shared__ float4 sP[];          /* 8192 * 16B = 128 KB */
    int b   = blockIdx.x >> 3;
    int sub = blockIdx.x & 7;
    const float* X = xyz + (size_t)b*NPTS*3;
    for (int p = threadIdx.x; p < NPTS; p += 1024)
        sP[p] = make_float4(X[p*3+0], X[p*3+1], X[p*3+2], 0.f);
    __syncthreads();
    int w = threadIdx.x >> 5, lane = threadIdx.x & 31;
    const float r2 = 0.04f;
#pragma unroll
    for (int ci = 0; ci < 4; ci++){
        int s   = sub*128 + w*4 + ci;
        int wid = b*NSEL + s;
        float cx = nx[wid*3+0], cy = nx[wid*3+1], cz = nx[wid*3+2];
        int* out = g_gidx + (size_t)wid*NSAMP;
        int cnt = 0, firstn = 0;
        for (int n0 = 0; n0 < NPTS; n0 += 32){
            float4 p = sP[n0 + lane];
            float d = dist3(p.x, p.y, p.z, cx, cy, cz);
            bool in = !(d > r2);
            unsigned m = __ballot_sync(0xffffffffu, in);
            if (m){
                if (cnt == 0) firstn = n0 + __ffs(m) - 1;
                int pre = __popc(m & ((1u << lane) - 1u));
                if (in && cnt + pre < NSAMP) out[cnt + pre] = n0 + lane;
                cnt += __popc(m);
                if (cnt >= NSAMP) break;
            }
        }
        for (int p = cnt + lane; p < NSAMP; p += 32) out[p] = firstn;
    }
}

/* ------------- GEMM layer 0 (gather, tf32 mma + 3-tap tail) ------------- */
__global__ __launch_bounds__(256) void k_gemm0(const float* __restrict__ xyz,
                                               const float* __restrict__ nx,
                                               const float* __restrict__ w,
                                               const float* __restrict__ bias)
{
    extern __shared__ float sm[];
    float* xs = sm;                       /* 256 * 68 (67 used) */
    float* wf = sm + 256*PAD;             /* 4096 fragment-ordered (k<64) */
    float* w3 = wf + 4096;                /* 3*64 tail weights (k=64..66) */
    __shared__ float sSum[64], sSq[64], sBias[64];
    int tid = threadIdx.x;
    if (tid < 64){ sSum[tid]=0.f; sSq[tid]=0.f; sBias[tid]=bias[tid]; }
    for (int i = tid; i < 4096; i += 256){
        int h = i & 1, ln = (i>>1)&31, pr = i>>6;
        int kb = pr>>3, nb = pr&7, gd = ln>>2, tg = ln&3;
        wf[i] = tf32r(w[(nb*8+gd)*67 + kb*8+tg + h*4]);
    }
    for (int i = tid; i < 192; i += 256){
        int kk = i >> 6, o = i & 63;
        w3[i] = tf32r(w[o*67 + 64 + kk]);
    }
    {   /* gather one row per thread */
        int gs  = blockIdx.x*8 + (tid >> 5);
        int k   = tid & 31;
        int b   = gs >> 10;
        int pid = g_gidx[gs*NSAMP + k];
        const float4* src = (const float4*)(g_ptsT + ((size_t)b*NPTS + pid)*64);
        float* xr = xs + tid*PAD;
#pragma unroll
        for (int q = 0; q < 16; q++){
            float4 v = src[q];
            xr[q*4+0]=tf32r(v.x); xr[q*4+1]=tf32r(v.y);
            xr[q*4+2]=tf32r(v.z); xr[q*4+3]=tf32r(v.w);
        }
        const float* P = xyz + ((size_t)b*NPTS + pid)*3;
        const float* C = nx + (size_t)gs*3;
        xr[64] = tf32r(__fsub_rn(P[0], C[0]));
        xr[65] = tf32r(__fsub_rn(P[1], C[1]));
        xr[66] = tf32r(__fsub_rn(P[2], C[2]));
    }
    __syncthreads();
    int lane = tid & 31, wp = tid >> 5;
    int gid = lane >> 2, tig = lane & 3;
    float sl[16], ql[16];
#pragma unroll
    for (int i = 0; i < 16; i++){ sl[i]=0.f; ql[i]=0.f; }
    size_t rbase = (size_t)blockIdx.x*256 + wp*32;
#pragma unroll
    for (int hh = 0; hh < 2; hh++){
        int lm0 = wp*32 + hh*16;
        float d[8][4];
#pragma unroll
        for (int nb = 0; nb < 8; nb++){
            d[nb][0]=sBias[nb*8+2*tig]; d[nb][1]=sBias[nb*8+2*tig+1];
            d[nb][2]=d[nb][0]; d[nb][3]=d[nb][1];
        }
#pragma unroll
        for (int kb = 0; kb < 8; kb++){
            const float* ar = xs + (lm0+gid)*PAD + kb*8 + tig;
            unsigned a0 = __float_as_uint(ar[0]);
            unsigned a2 = __float_as_uint(ar[4]);
            unsigned a1 = __float_as_uint(ar[8*PAD]);
            unsigned a3 = __float_as_uint(ar[8*PAD+4]);
#pragma unroll
            for (int nb = 0; nb < 8; nb++){
                float2 bp = *(const float2*)(wf + ((kb*8+nb)*32 + lane)*2);
                mma_tf32(d[nb][0], d[nb][1], d[nb][2], d[nb][3],
                         a0, a1, a2, a3,
                         __float_as_uint(bp.x), __float_as_uint(bp.y));
            }
        }
        /* 3-tap tail: k = 64..66 */
        {
            const float* xa = xs + (lm0+gid)*PAD + 64;
            const float* xb = xs + (lm0+gid+8)*PAD + 64;
            float xa0=xa[0], xa1=xa[1], xa2=xa[2];
            float xb0=xb[0], xb1=xb[1], xb2=xb[2];
#pragma unroll
            for (int nb = 0; nb < 8; nb++){
                int col = nb*8 + 2*tig;
                float w00=w3[col],     w01=w3[col+1];
                float w10=w3[64+col],  w11=w3[64+col+1];
                float w20=w3[128+col], w21=w3[128+col+1];
                d[nb][0] = fmaf(xa2,w20, fmaf(xa1,w10, fmaf(xa0,w00, d[nb][0])));
                d[nb][1] = fmaf(xa2,w21, fmaf(xa1,w11, fmaf(xa0,w01, d[nb][1])));
                d[nb][2] = fmaf(xb2,w20, fmaf(xb1,w10, fmaf(xb0,w00, d[nb][2])));
                d[nb][3] = fmaf(xb2,w21, fmaf(xb1,w11, fmaf(xb0,w01, d[nb][3])));
            }
        }
        size_t r0 = rbase + hh*16;
#pragma unroll
        for (int nb = 0; nb < 8; nb++){
            int col = nb*8 + 2*tig;
            *(float2*)(g_y0 + (r0+gid)*64   + col) = make_float2(d[nb][0], d[nb][1]);
            *(float2*)(g_y0 + (r0+gid+8)*64 + col) = make_float2(d[nb][2], d[nb][3]);
            sl[nb*2]   += d[nb][0]+d[nb][2];
            sl[nb*2+1] += d[nb][1]+d[nb][3];
            ql[nb*2]   = fmaf(d[nb][0],d[nb][0], fmaf(d[nb][2],d[nb][2], ql[nb*2]));
            ql[nb*2+1] = fmaf(d[nb][1],d[nb][1], fmaf(d[nb][3],d[nb][3], ql[nb*2+1]));
        }
    }
#pragma unroll
    for (int off = 4; off <= 16; off <<= 1)
#pragma unroll
        for (int i = 0; i < 16; i++){
            sl[i] += __shfl_xor_sync(0xffffffffu, sl[i], off);
            ql[i] += __shfl_xor_sync(0xffffffffu, ql[i], off);
        }
    if (gid == 0)
#pragma unroll
        for (int nb = 0; nb < 8; nb++){
            atomicAdd(&sSum[nb*8+2*tig],   sl[nb*2]);
            atomicAdd(&sSum[nb*8+2*tig+1], sl[nb*2+1]);
            atomicAdd(&sSq [nb*8+2*tig],   ql[nb*2]);
            atomicAdd(&sSq [nb*8+2*tig+1], ql[nb*2+1]);
        }
    __syncthreads();
    if (tid < 64){
        atomicAdd(&g_sum[0][tid], sSum[tid]);
        atomicAdd(&g_ssq[0][tid], sSq[tid]);
    }
}

/* ------------------- GEMM layer 1 (tf32 tensor mma) --------------------- */
/* affine fold for layer-0 BN computed in-prologue (k_affine removed)      */
__global__ __launch_bounds__(256) void k_gemm1(const float* __restrict__ w,
                                               const float* __restrict__ bias,
                                               const float* __restrict__ g,
                                               const float* __restrict__ beta)
{
    extern __shared__ float sm[];
    float* xs = sm;                       /* 256 * 68 */
    float* wf = sm + 256*PAD;             /* 4096 fragment-ordered */
    __shared__ float sSum[64], sSq[64], sA[64], sC[64], sBias[64];
    int tid = threadIdx.x;
    if (tid < 64){
        sSum[tid]=0.f; sSq[tid]=0.f; sBias[tid]=bias[tid];
        float a, c;
        affine_fold(g_sum[0][tid], g_ssq[0][tid], g[tid], beta[tid], a, c);
        sA[tid]=a; sC[tid]=c;
    }
    for (int i = tid; i < 4096; i += 256){
        int h = i & 1, ln = (i>>1)&31, pr = i>>6;
        int kb = pr>>3, nb = pr&7, gd = ln>>2, tg = ln&3;
        wf[i] = tf32r(w[(nb*8+gd)*64 + kb*8+tg + h*4]);
    }
    __syncthreads();
    {
        size_t row = (size_t)blockIdx.x*256 + tid;
        const float4* src = (const float4*)(g_y0 + row*64);
        float* xr = xs + tid*PAD;
#pragma unroll
        for (int q = 0; q < 16; q++){
            float4 v = src[q];
            xr[q*4+0]=tf32r(fmaxf(fmaf(sA[q*4+0],v.x,sC[q*4+0]),0.f));
            xr[q*4+1]=tf32r(fmaxf(fmaf(sA[q*4+1],v.y,sC[q*4+1]),0.f));
            xr[q*4+2]=tf32r(fmaxf(fmaf(sA[q*4+2],v.z,sC[q*4+2]),0.f));
            xr[q*4+3]=tf32r(fmaxf(fmaf(sA[q*4+3],v.w,sC[q*4+3]),0.f));
        }
    }
    __syncthreads();
    int lane = tid & 31, wp = tid >> 5;
    int gid = lane >> 2, tig = lane & 3;
    float sl[16], ql[16];
#pragma unroll
    for (int i = 0; i < 16; i++){ sl[i]=0.f; ql[i]=0.f; }
    size_t rbase = (size_t)blockIdx.x*256 + wp*32;
#pragma unroll
    for (int hh = 0; hh < 2; hh++){
        int lm0 = wp*32 + hh*16;
        float d[8][4];
#pragma unroll
        for (int nb = 0; nb < 8; nb++){
            d[nb][0]=sBias[nb*8+2*tig]; d[nb][1]=sBias[nb*8+2*tig+1];
            d[nb][2]=d[nb][0]; d[nb][3]=d[nb][1];
        }
#pragma unroll
        for (int kb = 0; kb < 8; kb++){
            const float* ar = xs + (lm0+gid)*PAD + kb*8 + tig;
            unsigned a0 = __float_as_uint(ar[0]);
            unsigned a2 = __float_as_uint(ar[4]);
            unsigned a1 = __float_as_uint(ar[8*PAD]);
            unsigned a3 = __float_as_uint(ar[8*PAD+4]);
#pragma unroll
            for (int nb = 0; nb < 8; nb++){
                float2 bp = *(const float2*)(wf + ((kb*8+nb)*32 + lane)*2);
                mma_tf32(d[nb][0], d[nb][1], d[nb][2], d[nb][3],
                         a0, a1, a2, a3,
                         __float_as_uint(bp.x), __float_as_uint(bp.y));
            }
        }
        size_t r0 = rbase + hh*16;
#pragma unroll
        for (int nb = 0; nb < 8; nb++){
            int col = nb*8 + 2*tig;
            *(float2*)(g_y1 + (r0+gid)*64   + col) = make_float2(d[nb][0], d[nb][1]);
            *(float2*)(g_y1 + (r0+gid+8)*64 + col) = make_float2(d[nb][2], d[nb][3]);
            sl[nb*2]   += d[nb][0]+d[nb][2];
            sl[nb*2+1] += d[nb][1]+d[nb][3];
            ql[nb*2]   = fmaf(d[nb][0],d[nb][0], fmaf(d[nb][2],d[nb][2], ql[nb*2]));
            ql[nb*2+1] = fmaf(d[nb][1],d[nb][1], fmaf(d[nb][3],d[nb][3], ql[nb*2+1]));
        }
    }
#pragma unroll
    for (int off = 4; off <= 16; off <<= 1)
#pragma unroll
        for (int i = 0; i < 16; i++){
            sl[i] += __shfl_xor_sync(0xffffffffu, sl[i], off);
            ql[i] += __shfl_xor_sync(0xffffffffu, ql[i], off);
        }
    if (gid == 0)
#pragma unroll
        for (int nb = 0; nb < 8; nb++){
            atomicAdd(&sSum[nb*8+2*tig],   sl[nb*2]);
            atomicAdd(&sSum[nb*8+2*tig+1], sl[nb*2+1]);
            atomicAdd(&sSq [nb*8+2*tig],   ql[nb*2]);
            atomicAdd(&sSq [nb*8+2*tig+1], ql[nb*2+1]);
        }
    __syncthreads();
    if (tid < 64){
        atomicAdd(&g_sum[1][tid], sSum[tid]);
        atomicAdd(&g_ssq[1][tid], sSq[tid]);
    }
}

/* --------------- GEMM layer 2 (tf32 mma, max/min fused) ----------------- */
__global__ __launch_bounds__(256) void k_gemm2(const float* __restrict__ w,
                                               const float* __restrict__ bias,
                                               const float* __restrict__ g,
                                               const float* __restrict__ beta)
{
    extern __shared__ float sm[];
    float* xs = sm;
    float* wf = sm + 256*PAD;
    __shared__ float sSum[64], sSq[64], sA[64], sC[64], sBias[64];
    int tid = threadIdx.x;
    int half = blockIdx.y;
    if (tid < 64){
        sSum[tid]=0.f; sSq[tid]=0.f; sBias[tid]=bias[half*64+tid];
        float a, c;
        affine_fold(g_sum[1][tid], g_ssq[1][tid], g[tid], beta[tid], a, c);
        sA[tid]=a; sC[tid]=c;
    }
    for (int i = tid; i < 4096; i += 256){
        int h = i & 1, ln = (i>>1)&31, pr = i>>6;
        int kb = pr>>3, nb = pr&7, gd = ln>>2, tg = ln&3;
        wf[i] = tf32r(w[(size_t)(half*64 + nb*8+gd)*64 + kb*8+tg + h*4]);
    }
    __syncthreads();
    {
        size_t row = (size_t)blockIdx.x*256 + tid;
        const float4* src = (const float4*)(g_y1 + row*64);
        float* xr = xs + tid*PAD;
#pragma unroll
        for (int q = 0; q < 16; q++){
            float4 v = src[q];
            xr[q*4+0]=tf32r(fmaxf(fmaf(sA[q*4+0],v.x,sC[q*4+0]),0.f));
            xr[q*4+1]=tf32r(fmaxf(fmaf(sA[q*4+1],v.y,sC[q*4+1]),0.f));
            xr[q*4+2]=tf32r(fmaxf(fmaf(sA[q*4+2],v.z,sC[q*4+2]),0.f));
            xr[q*4+3]=tf32r(fmaxf(fmaf(sA[q*4+3],v.w,sC[q*4+3]),0.f));
        }
    }
    __syncthreads();
    int lane = tid & 31, wp = tid >> 5;
    int gid = lane >> 2, tig = lane & 3;
    float sl[16], ql[16], mx[16], mn[16];
#pragma unroll
    for (int i = 0; i < 16; i++){ sl[i]=0.f; ql[i]=0.f; mx[i]=-3.4e38f; mn[i]=3.4e38f; }
#pragma unroll
    for (int hh = 0; hh < 2; hh++){
        int lm0 = wp*32 + hh*16;
        float d[8][4];
#pragma unroll
        for (int nb = 0; nb < 8; nb++){
            d[nb][0]=sBias[nb*8+2*tig]; d[nb][1]=sBias[nb*8+2*tig+1];
            d[nb][2]=d[nb][0]; d[nb][3]=d[nb][1];
        }
#pragma unroll
        for (int kb = 0; kb < 8; kb++){
            const float* ar = xs + (lm0+gid)*PAD + kb*8 + tig;
            unsigned a0 = __float_as_uint(ar[0]);
            unsigned a2 = __float_as_uint(ar[4]);
            unsigned a1 = __float_as_uint(ar[8*PAD]);
            unsigned a3 = __float_as_uint(ar[8*PAD+4]);
#pragma unroll
            for (int nb = 0; nb < 8; nb++){
                float2 bp = *(const float2*)(wf + ((kb*8+nb)*32 + lane)*2);
                mma_tf32(d[nb][0], d[nb][1], d[nb][2], d[nb][3],
                         a0, a1, a2, a3,
                         __float_as_uint(bp.x), __float_as_uint(bp.y));
            }
        }
#pragma unroll
        for (int nb = 0; nb < 8; nb++){
            sl[nb*2]   += d[nb][0]+d[nb][2];
            sl[nb*2+1] += d[nb][1]+d[nb][3];
            ql[nb*2]   = fmaf(d[nb][0],d[nb][0], fmaf(d[nb][2],d[nb][2], ql[nb*2]));
            ql[nb*2+1] = fmaf(d[nb][1],d[nb][1], fmaf(d[nb][3],d[nb][3], ql[nb*2+1]));
            mx[nb*2]   = fmaxf(mx[nb*2],   fmaxf(d[nb][0], d[nb][2]));
            mx[nb*2+1] = fmaxf(mx[nb*2+1], fmaxf(d[nb][1], d[nb][3]));
            mn[nb*2]   = fminf(mn[nb*2],   fminf(d[nb][0], d[nb][2]));
            mn[nb*2+1] = fminf(mn[nb*2+1], fminf(d[nb][1], d[nb][3]));
        }
    }
#pragma unroll
    for (int off = 4; off <= 16; off <<= 1)
#pragma unroll
        for (int i = 0; i < 16; i++){
            sl[i] += __shfl_xor_sync(0xffffffffu, sl[i], off);
            ql[i] += __shfl_xor_sync(0xffffffffu, ql[i], off);
            mx[i]  = fmaxf(mx[i], __shfl_xor_sync(0xffffffffu, mx[i], off));
            mn[i]  = fminf(mn[i], __shfl_xor_sync(0xffffffffu, mn[i], off));
        }
    if (gid == 0){
        int grp = blockIdx.x*8 + wp;
        float* M = g_max2 + (size_t)grp*128 + half*64;
        float* m = g_min2 + (size_t)grp*128 + half*64;
#pragma unroll
        for (int nb = 0; nb < 8; nb++){
            int col = nb*8 + 2*tig;
            *(float2*)(M + col) = make_float2(mx[nb*2], mx[nb*2+1]);
            *(float2*)(m + col) = make_float2(mn[nb*2], mn[nb*2+1]);
            atomicAdd(&sSum[col],   sl[nb*2]);
            atomicAdd(&sSum[col+1], sl[nb*2+1]);
            atomicAdd(&sSq [col],   ql[nb*2]);
            atomicAdd(&sSq [col+1], ql[nb*2+1]);
        }
    }
    __syncthreads();
    if (tid < 64){
        atomicAdd(&g_sum[2][half*64+tid], sSum[tid]);
        atomicAdd(&g_ssq[2][half*64+tid], sSq[tid]);
    }
}

/* ----------------------- final BN+relu+max -> (B,128,1024) -------------- */
/* layer-2 affine fold computed per block (one channel per 256-thr block)  */
__global__ void k_out(float* __restrict__ out,
                      const float* __restrict__ g,
                      const float* __restrict__ beta)
{
    __shared__ float sa, sc;
    int idx = blockIdx.x*blockDim.x + threadIdx.x;
    int o = (idx >> 10) & 127;
    if (threadIdx.x == 0){
        float a, c;
        affine_fold(g_sum[2][o], g_ssq[2][o], g[o], beta[o], a, c);
        sa = a; sc = c;
    }
    __syncthreads();
    int b = idx >> 17, s = idx & 1023;
    float a = sa, c = sc;
    size_t gi = ((size_t)(b*NSEL + s))*128 + o;
    float v = (a >= 0.f) ? g_max2[gi] : g_min2[gi];
    out[idx] = fmaxf(fmaf(a, v, c), 0.f);
}

/* ------------------------------- launch --------------------------------- */
extern "C" void kernel_launch(void* const* d_in, const int* in_sizes, int n_in,
                              void* d_out, int out_size)
{
    (void)in_sizes; (void)n_in; (void)out_size;
    const float* xyz = (const float*)d_in[0];
    const float* pts = (const float*)d_in[1];
    const float* w0  = (const float*)d_in[2];
    const float* b0  = (const float*)d_in[3];
    const float* gg0 = (const float*)d_in[4];
    const float* be0 = (const float*)d_in[5];
    const float* w1  = (const float*)d_in[6];
    const float* b1  = (const float*)d_in[7];
    const float* gg1 = (const float*)d_in[8];
    const float* be1 = (const float*)d_in[9];
    const float* w2  = (const float*)d_in[10];
    const float* b2  = (const float*)d_in[11];
    const float* gg2 = (const float*)d_in[12];
    const float* be2 = (const float*)d_in[13];
    float* out    = (float*)d_out;
    float* newxyz = out;                       /* 16*1024*3 */
    float* newpts = out + BATCH*NSEL*3;        /* 16*128*1024 */

    const int SM_PTS = NPTS * 16;                       /* 131072 */
    const int SM_G0  = (256*PAD + 4096 + 192) * 4;      /* 86784  */
    const int SM_MMA = (256*PAD + 4096) * 4;            /* 86016  */
    cudaFuncSetAttribute(k_fps,   cudaFuncAttributeMaxDynamicSharedMemorySize, SM_PTS);
    cudaFuncSetAttribute(k_ball,  cudaFuncAttributeMaxDynamicSharedMemorySize, SM_PTS);
    cudaFuncSetAttribute(k_gemm0, cudaFuncAttributeMaxDynamicSharedMemorySize, SM_G0);
    cudaFuncSetAttribute(k_gemm1, cudaFuncAttributeMaxDynamicSharedMemorySize, SM_MMA);
    cudaFuncSetAttribute(k_gemm2, cudaFuncAttributeMaxDynamicSharedMemorySize, SM_MMA);

    k_zero<<<1, 128>>>();
    k_fps <<<BATCH, 1024, SM_PTS>>>(xyz, newxyz);
    k_tr  <<<dim3(NPTS/32, 2, BATCH), dim3(32, 8)>>>(pts);
    k_ball<<<BATCH*8, 1024, SM_PTS>>>(xyz, newxyz);
    k_gemm0<<<NROWS/256, 256, SM_G0>>>(xyz, newxyz, w0, b0);
    k_gemm1<<<NROWS/256, 256, SM_MMA>>>(w1, b1, gg0, be0);
    k_gemm2<<<dim3(NROWS/256, 2), 256, SM_MMA>>>(w2, b2, gg1, be1);
    k_out<<<(BATCH*128*NSEL)/256, 256>>>(newpts, gg2, be2);
}